// round 14
// baseline (speedup 1.0000x reference)
#include <cuda_runtime.h>
#include <cuda_bf16.h>
#include <cstdint>

#define NN 50000
#define F1 128
#define F2 16
#define EMAX 850016

__device__ __align__(16) float g_dinv[NN];
__device__ __align__(16) float g_h1  [NN * F1];
__device__ __align__(16) float g_agg1[NN * F1];
__device__ __align__(16) float g_h2  [NN * F2];
__device__ int g_cnt[NN];
__device__ int g_rowptr[NN + 1];
__device__ int g_woff[NN];
__device__ int g_esrc[EMAX];
__device__ int g_is32 = 0;   // never reset: 0 = int64 edges, 1 = int32. Idempotent across replays.

// Decode edge endpoint j (buffer is int32[2E] or int64[2E]); clamp keeps errors finite.
__device__ __forceinline__ int edge_at(const void* eiv, int j, bool is32) {
    long long v = is32 ? (long long)((const int*)eiv)[j]
                       : ((const long long*)eiv)[j];
    if (v < 0) v = 0;
    if (v >= NN) v = NN - 1;
    return (int)v;
}

// ---------------------------------------------------------------- init: zero degree counts + detect dtype
__global__ void k_init(const int* __restrict__ ei32, int E) {
    int i = blockIdx.x * blockDim.x + threadIdx.x;
    int stride = gridDim.x * blockDim.x;
    for (int j = i; j < NN; j += stride) g_cnt[j] = 0;
    // dtype probe: reading int32[2E] never over-reads; int64 values < 2^31 have zero odd words
    for (int j = i; j < E; j += stride) {
        if (ei32[2 * j + 1] != 0) g_is32 = 1;   // benign race; only ever set to 1
    }
}

// ---------------------------------------------------------------- degree (int counts)
__global__ void k_deg(const void* __restrict__ eiv, int E) {
    bool is32 = (g_is32 != 0);
    int e = blockIdx.x * blockDim.x + threadIdx.x;
    if (e < E) atomicAdd(&g_cnt[edge_at(eiv, E + e, is32)], 1);
}

__global__ void k_dinv(int n) {
    int i = blockIdx.x * blockDim.x + threadIdx.x;
    if (i < n) g_dinv[i] = rsqrtf(fmaxf((float)g_cnt[i], 1.0f));
}

// ---------------------------------------------------------------- exclusive scan of counts -> rowptr (+ woff copy)
__global__ void k_scan() {
    __shared__ int partial[1024];
    const int CH = (NN + 1023) / 1024;    // 49
    int t = threadIdx.x;
    int base = t * CH;
    int s = 0;
    for (int i = 0; i < CH; i++) {
        int idx = base + i;
        if (idx < NN) s += g_cnt[idx];
    }
    partial[t] = s;
    __syncthreads();
    for (int off = 1; off < 1024; off <<= 1) {
        int v = 0;
        if (t >= off) v = partial[t - off];
        __syncthreads();
        if (t >= off) partial[t] += v;
        __syncthreads();
    }
    int run = (t == 0) ? 0 : partial[t - 1];
    for (int i = 0; i < CH; i++) {
        int idx = base + i;
        if (idx < NN) {
            g_rowptr[idx] = run;
            g_woff[idx]   = run;
            run += g_cnt[idx];
        }
    }
    if (t == 1023) g_rowptr[NN] = partial[1023];
}

// ---------------------------------------------------------------- edge placement: CSR by dst
__global__ void k_place(const void* __restrict__ eiv, int E) {
    bool is32 = (g_is32 != 0);
    int e = blockIdx.x * blockDim.x + threadIdx.x;
    if (e >= E) return;
    int src = edge_at(eiv, e, is32);
    int dst = edge_at(eiv, E + e, is32);
    int slot = atomicAdd(&g_woff[dst], 1);
    g_esrc[slot] = src;
}

// ---------------------------------------------------------------- GEMM1 (tf32 tensor cores): h1 = x @ W1
#define BP 136   // smem row pitch: bank = tig*8+gid -> conflict-free

__device__ __forceinline__ uint32_t f2tf32(float v) {
    uint32_t r;
    asm("cvt.rna.tf32.f32 %0, %1;" : "=r"(r) : "f"(v));
    return r;
}

__global__ __launch_bounds__(256) void k_gemm1_tc(const float* __restrict__ A,
                                                  const float* __restrict__ W, int M) {
    __shared__ float Bs[8][BP];
    int tid  = threadIdx.x;
    int warp = tid >> 5;
    int lane = tid & 31;
    int gid  = lane >> 2;
    int tig  = lane & 3;
    int row0 = blockIdx.x * 128 + warp * 16;

    float c[16][4];
    #pragma unroll
    for (int i = 0; i < 16; i++) { c[i][0] = c[i][1] = c[i][2] = c[i][3] = 0.f; }

    for (int k0 = 0; k0 < 128; k0 += 8) {
        __syncthreads();
        #pragma unroll
        for (int i = tid; i < 8 * 128; i += 256) {
            int kr = i >> 7;
            int nc = i & 127;
            Bs[kr][nc] = __uint_as_float(f2tf32(W[(k0 + kr) * 128 + nc]));
        }
        __syncthreads();

        int ra = row0 + gid, rb = ra + 8;
        uint32_t a0 = f2tf32((ra < M) ? A[ra * 128 + k0 + tig]     : 0.f);
        uint32_t a1 = f2tf32((rb < M) ? A[rb * 128 + k0 + tig]     : 0.f);
        uint32_t a2 = f2tf32((ra < M) ? A[ra * 128 + k0 + tig + 4] : 0.f);
        uint32_t a3 = f2tf32((rb < M) ? A[rb * 128 + k0 + tig + 4] : 0.f);

        #pragma unroll
        for (int nb = 0; nb < 16; nb++) {
            int n0 = nb * 8;
            uint32_t b0 = __float_as_uint(Bs[tig]    [n0 + gid]);
            uint32_t b1 = __float_as_uint(Bs[tig + 4][n0 + gid]);
            asm volatile(
                "mma.sync.aligned.m16n8k8.row.col.f32.tf32.tf32.f32 "
                "{%0,%1,%2,%3}, {%4,%5,%6,%7}, {%8,%9}, {%0,%1,%2,%3};"
                : "+f"(c[nb][0]), "+f"(c[nb][1]), "+f"(c[nb][2]), "+f"(c[nb][3])
                : "r"(a0), "r"(a1), "r"(a2), "r"(a3), "r"(b0), "r"(b1));
        }
    }

    int r0 = row0 + gid, r1 = r0 + 8;
    #pragma unroll
    for (int nb = 0; nb < 16; nb++) {
        int col = nb * 8 + tig * 2;
        if (r0 < M) *(float2*)(g_h1 + r0 * 128 + col) = make_float2(c[nb][0], c[nb][1]);
        if (r1 < M) *(float2*)(g_h1 + r1 * 128 + col) = make_float2(c[nb][2], c[nb][3]);
    }
}

// ---------------------------------------------------------------- gather layer 1: warp per dst node, no atomics
__global__ void k_gather1(int n) {
    int w = (blockIdx.x * blockDim.x + threadIdx.x) >> 5;
    int lane = threadIdx.x & 31;
    if (w >= n) return;
    int beg = g_rowptr[w], end = g_rowptr[w + 1];
    float dv = g_dinv[w];
    float4 acc = make_float4(0.f, 0.f, 0.f, 0.f);
    for (int j = beg; j < end; j++) {
        int src = g_esrc[j];
        float nm = dv * g_dinv[src];
        float4 v = *(const float4*)(g_h1 + src * 128 + lane * 4);
        acc.x += nm * v.x; acc.y += nm * v.y; acc.z += nm * v.z; acc.w += nm * v.w;
    }
    *(float4*)(g_agg1 + w * 128 + lane * 4) = acc;
}

// ---------------------------------------------------------------- GEMM2: h2 = relu(agg1 + b1) @ W2
__global__ void k_gemm2(const float* __restrict__ W2, const float* __restrict__ b1, int M) {
    __shared__ float Ws[128 * 16];
    __shared__ float Zs[16][128];
    int tid = threadIdx.x;
    int row0 = blockIdx.x * 16;

    #pragma unroll
    for (int i = 0; i < 8; i++) Ws[tid * 8 + i] = W2[tid * 8 + i];

    {
        int zr = tid >> 4;
        int zc = (tid & 15) * 8;
        int r = row0 + zr;
        #pragma unroll
        for (int i = 0; i < 8; i++) {
            float val = 0.f;
            if (r < M) val = fmaxf(g_agg1[r * 128 + zc + i] + b1[zc + i], 0.f);
            Zs[zr][zc + i] = val;
        }
    }
    __syncthreads();

    int r = tid >> 4;
    int c = tid & 15;
    float acc = 0.f;
    #pragma unroll
    for (int k = 0; k < 128; k++)
        acc += Zs[r][k] * Ws[k * 16 + c];

    int row = row0 + r;
    if (row < M) g_h2[row * 16 + c] = acc;
}

// ---------------------------------------------------------------- gather layer 2: 16 lanes per node, writes out directly
__global__ void k_gather2(float* __restrict__ out, int n) {
    int gid = blockIdx.x * blockDim.x + threadIdx.x;
    int node = gid >> 4;
    int l = gid & 15;
    if (node >= n) return;
    int beg = g_rowptr[node], end = g_rowptr[node + 1];
    float dv = g_dinv[node];
    float acc = 0.f;
    for (int j = beg; j < end; j++) {
        int src = g_esrc[j];
        acc += dv * g_dinv[src] * g_h2[src * 16 + l];
    }
    out[node * 16 + l] = acc;
}

// ---------------------------------------------------------------- log_softmax rows of 16 (+ b2), in place
__global__ void k_lsm(float* __restrict__ out, const float* __restrict__ b2, int n) {
    int r = blockIdx.x * blockDim.x + threadIdx.x;
    if (r >= n) return;
    float v[16];
    #pragma unroll
    for (int j = 0; j < 16; j += 4) {
        float4 t = *(const float4*)(out + r * 16 + j);
        v[j + 0] = t.x + b2[j + 0];
        v[j + 1] = t.y + b2[j + 1];
        v[j + 2] = t.z + b2[j + 2];
        v[j + 3] = t.w + b2[j + 3];
    }
    float m = v[0];
    #pragma unroll
    for (int j = 1; j < 16; j++) m = fmaxf(m, v[j]);
    float s = 0.f;
    #pragma unroll
    for (int j = 0; j < 16; j++) s += expf(v[j] - m);
    float ls = logf(s) + m;
    #pragma unroll
    for (int j = 0; j < 16; j += 4) {
        float4 t = make_float4(v[j] - ls, v[j + 1] - ls, v[j + 2] - ls, v[j + 3] - ls);
        *(float4*)(out + r * 16 + j) = t;
    }
}

// ================================================================ launch
extern "C" void kernel_launch(void* const* d_in, const int* in_sizes, int n_in,
                              void* d_out, int out_size) {
    // Resolve inputs BY ELEMENT COUNT (ordering-independent).
    const float* x  = nullptr;
    const void*  ei = nullptr;
    const float* W1 = nullptr;
    const float* b1 = nullptr;
    const float* W2 = nullptr;
    const float* b2 = nullptr;
    int x_sz = 0, ei_sz = 0;

    for (int i = 0; i < n_in; i++) {
        int s = in_sizes[i];
        if (s == 16)                 b2 = (const float*)d_in[i];
        else if (s == 128)           b1 = (const float*)d_in[i];
        else if (s == 2048)          W2 = (const float*)d_in[i];
        else if (s == 16384)         W1 = (const float*)d_in[i];
        else if (s == 1700000)     { ei = d_in[i];               ei_sz = s; }
        else                       { x  = (const float*)d_in[i]; x_sz  = s; }
    }
    float* out = (float*)d_out;

    int M = x_sz / F1;         // 50000 nodes
    int E = ei_sz / 2;         // 850000 edges (incl. self loops)

    // 1. zero degree counts + dtype probe
    k_init<<<512, 256>>>((const int*)ei, E);

    // 2. int degree histogram
    k_deg<<<(E + 255) / 256, 256>>>(ei, E);

    // 3. dinv from counts
    k_dinv<<<(M + 255) / 256, 256>>>(M);

    // 4. CSR rowptr (single-block scan)
    k_scan<<<1, 1024>>>();

    // 5. edge placement into CSR
    k_place<<<(E + 255) / 256, 256>>>(ei, E);

    // 6. GEMM1 (tf32): h1 = x @ W1
    k_gemm1_tc<<<(M + 127) / 128, 256>>>(x, W1, M);

    // 7. gather layer 1 (warp per node)
    k_gather1<<<(M * 32 + 255) / 256, 256>>>(M);

    // 8. GEMM2 with fused bias+relu
    k_gemm2<<<(M + 15) / 16, 256>>>(W2, b1, M);

    // 9. gather layer 2 (16 lanes per node) -> writes out fully
    k_gather2<<<(M * 16 + 255) / 256, 256>>>(out, M);

    // 10. bias2 + log_softmax in place
    k_lsm<<<(M + 255) / 256, 256>>>(out, b2, M);
}